// round 15
// baseline (speedup 1.0000x reference)
#include <cuda_runtime.h>
#include <cuda_fp16.h>
#include <math.h>
#include <stdint.h>

// B=1024, D=512, N=16, H=512, M = N*B = 16384
#define DD   512
#define NN   16
#define HH   512
#define MTOT 16384

// Slotted fp16 fragment files (u32 = packed half2).
// A files: [tile(128)][kc(16)][slot(16)][128]; slot = mf*2+ks.
// B files: [blk][kc(16)][slot(16)][128];     slot = n16*2+ks.
__device__ uint32_t g_A1[128 * 16 * 16 * 128];   // x (gathered), GEMM1 A
__device__ uint32_t g_A2[128 * 16 * 16 * 128];   // lrelu(X@Ws1+bs1), GEMM2 A
__device__ uint32_t g_A3[128 * 16 * 16 * 128];   // shared, GEMM3 A (r-ordered)
__device__ uint32_t g_WB1[4  * 16 * 16 * 128];   // Ws1 slotted
__device__ uint32_t g_WB2[4  * 16 * 16 * 128];   // Ws2 slotted
__device__ uint32_t g_Bh [64 * 16 * 16 * 128];   // Wc1 slotted [n*4+hb]

__device__ __forceinline__ float lrelu(float v) { return v >= 0.f ? v : 0.1f * v; }
__device__ __forceinline__ uint32_t pack_h2(float lo, float hi) {
    __half2 h = __floats2half2_rn(lo, hi);
    return *reinterpret_cast<uint32_t*>(&h);
}
__device__ __forceinline__ uint32_t smem_u32(const void* p) {
    uint32_t a;
    asm("{ .reg .u64 t; cvta.to.shared.u64 t, %1; cvt.u32.u64 %0, t; }" : "=r"(a) : "l"(p));
    return a;
}
__device__ __forceinline__ void cpcg16(uint32_t dst, const void* src) {
    asm volatile("cp.async.cg.shared.global [%0], [%1], 16;" :: "r"(dst), "l"(src));
}
__device__ __forceinline__ void cp_commit() {
    asm volatile("cp.async.commit_group;" ::: "memory");
}
template <int N>
__device__ __forceinline__ void cp_wait() {
    asm volatile("cp.async.wait_group %0;" :: "n"(N) : "memory");
}
__device__ __forceinline__ void mma16h(float* c, const uint32_t* a,
                                       uint32_t b0, uint32_t b1) {
    asm volatile(
        "mma.sync.aligned.m16n8k16.row.col.f32.f16.f16.f32 "
        "{%0,%1,%2,%3}, {%4,%5,%6,%7}, {%8,%9}, {%0,%1,%2,%3};"
        : "+f"(c[0]), "+f"(c[1]), "+f"(c[2]), "+f"(c[3])
        : "r"(a[0]), "r"(a[1]), "r"(a[2]), "r"(a[3]), "r"(b0), "r"(b1));
}

#define SLOTU 128
#define BUFU  2048          // u32 per (kc) buffer: 16 slots * 128
#define RING_SMEM 65536     // 4-ring x (A 8KB + B 8KB)

// ===========================================================================
// Fused prep + zero kernel, v2: coalesced loads -> smem tile -> coalesced
// slotted stores. Slot formulas identical to R11-R14 (applied to smem).
// Block ranges: [0,1024) xA per-b; [1024,2048) Wc1 (n,hb,kc);
//               [2048,2176) Ws1/Ws2 (which,hb,kc); [2176,3200) zero.
// ===========================================================================
__global__ __launch_bounds__(256)
void prep_all_kernel(const float* __restrict__ x,
                     const float* __restrict__ Ws1,
                     const float* __restrict__ Ws2,
                     const float* __restrict__ Wc1,
                     float* __restrict__ out)
{
    __shared__ float sf[16 * 517];      // xA: [n][k], pitch 517
    __shared__ float f2[32 * 130];      // W tiles: [kk][c], pitch 130
    const int blk = blockIdx.x;
    const int tid = threadIdx.x;

    if (blk < 1024) {
        // --- xA: one b per block. r = b*16+n -> tile = b>>3, mf = b&7. ---
        const int b = blk;
        #pragma unroll
        for (int i = 0; i < 32; i++) {
            int e = tid + i * 256;                 // < 8192, coalesced
            int k = e >> 4, n = e & 15;
            sf[n * 517 + k] = x[(size_t)b * 8192 + e];
        }
        __syncthreads();
        const int tile = b >> 3, mf = b & 7;
        #pragma unroll
        for (int i = 0; i < 16; i++) {
            int e2 = tid + i * 256;                // < 4096
            int i128 = e2 & 127, ks = (e2 >> 7) & 1, kc = e2 >> 8;
            int t = i128 >> 2, j = i128 & 3;
            int n = ((j & 1) << 3) + (t >> 2);
            int k = kc * 32 + ks * 16 + (((j >> 1) & 1) << 3) + 2 * (t & 3);
            g_A1[(((size_t)(tile * 16 + kc)) * 16 + (mf * 2 + ks)) * 128 + i128]
                = pack_h2(sf[n * 517 + k], sf[n * 517 + k + 1]);
        }
    } else if (blk < 2048) {
        // --- Wc1 -> g_Bh: one (n, hb, kc) per block. ---
        const int q = blk - 1024;
        const int n = q >> 6, hb = (q >> 4) & 3, kc = q & 15;
        const float* W = Wc1 + (size_t)n * DD * HH;
        #pragma unroll
        for (int i = 0; i < 16; i++) {
            int e = tid + i * 256;                 // < 4096, coalesced rows
            int kk = e >> 7, c = e & 127;
            f2[kk * 130 + c] = W[(size_t)(kc * 32 + kk) * HH + hb * 128 + c];
        }
        __syncthreads();
        #pragma unroll
        for (int i = 0; i < 8; i++) {
            int e = tid + i * 256;                 // < 2048
            int i128 = e & 127, s = e >> 7;
            int n16 = s >> 1, ks = s & 1;
            int t = i128 >> 2, j = i128 & 3;
            int nc = n16 * 16 + (((j >> 1) & 1) << 3) + (t >> 2);
            int kk = ks * 16 + ((j & 1) << 3) + 2 * (t & 3);
            g_Bh[(((size_t)((n * 4 + hb) * 16 + kc)) * 16 + s) * 128 + i128]
                = pack_h2(f2[kk * 130 + nc], f2[(kk + 1) * 130 + nc]);
        }
    } else if (blk < 2176) {
        // --- Ws1/Ws2 -> g_WB1/2: one (which, hb, kc) per block. ---
        const int q = blk - 2048;
        const int which = q >> 6, hb = (q >> 4) & 3, kc = q & 15;
        const float* W = which ? Ws2 : Ws1;
        uint32_t* dst  = which ? g_WB2 : g_WB1;
        #pragma unroll
        for (int i = 0; i < 16; i++) {
            int e = tid + i * 256;
            int kk = e >> 7, c = e & 127;
            f2[kk * 130 + c] = W[(size_t)(kc * 32 + kk) * DD + hb * 128 + c];
        }
        __syncthreads();
        #pragma unroll
        for (int i = 0; i < 8; i++) {
            int e = tid + i * 256;
            int i128 = e & 127, s = e >> 7;
            int n16 = s >> 1, ks = s & 1;
            int t = i128 >> 2, j = i128 & 3;
            int nc = n16 * 16 + (((j >> 1) & 1) << 3) + (t >> 2);
            int kk = ks * 16 + ((j & 1) << 3) + 2 * (t & 3);
            dst[(((size_t)(hb * 16 + kc)) * 16 + s) * 128 + i128]
                = pack_h2(f2[kk * 130 + nc], f2[(kk + 1) * 130 + nc]);
        }
    } else {
        // --- zero full_out accumulation region ---
        int i = (blk - 2176) * 256 + tid;          // exactly covers 262144
        (out + MTOT)[i] = 0.f;
    }
}

// ===========================================================================
// Shared mainloop: 4-deep ring, one sync per kc, early stage() issue.
// Single fragment set live at a time (register-lean for 3 CTAs/SM).
// ===========================================================================
struct Core {
    const uint32_t* srcA;
    const uint32_t* srcB;
    uint32_t* Ab[4];
    uint32_t* Bb[4];
    int tid, lane, wm, wn;

    __device__ __forceinline__ void stage(int kc) {
        const int buf = kc & 3;
        const uint32_t* sa = srcA + kc * BUFU;
        const uint32_t* sb = srcB + kc * BUFU;
        uint32_t da = smem_u32(Ab[buf]);
        uint32_t db = smem_u32(Bb[buf]);
        #pragma unroll
        for (int i = 0; i < 4; i++) {
            int ch = tid + i * 128;
            cpcg16(da + ch * 16, sa + ch * 4);
            cpcg16(db + ch * 16, sb + ch * 4);
        }
        cp_commit();
    }

    __device__ __forceinline__ void ldfrag(const uint32_t* Asl, const uint32_t* Bsl,
                                           int ks, uint4* af, uint4* bf) {
        #pragma unroll
        for (int mfl = 0; mfl < 4; mfl++)
            af[mfl] = *reinterpret_cast<const uint4*>(
                &Asl[((wm * 4 + mfl) * 2 + ks) * SLOTU + lane * 4]);
        #pragma unroll
        for (int np = 0; np < 4; np++)
            bf[np] = *reinterpret_cast<const uint4*>(
                &Bsl[((wn * 4 + np) * 2 + ks) * SLOTU + lane * 4]);
    }

    __device__ __forceinline__ void domma(const uint4* af, const uint4* bf,
                                          float c[4][8][4]) {
        #pragma unroll
        for (int np = 0; np < 4; np++) {
            #pragma unroll
            for (int mfl = 0; mfl < 4; mfl++) {
                const uint32_t* aa = reinterpret_cast<const uint32_t*>(&af[mfl]);
                mma16h(c[mfl][2 * np + 0], aa, bf[np].x, bf[np].y);
                mma16h(c[mfl][2 * np + 1], aa, bf[np].z, bf[np].w);
            }
        }
    }

    __device__ __forceinline__ void run(float c[4][8][4]) {
        stage(0); stage(1); stage(2);
        for (int kc = 0; kc < 16; kc++) {
            if (kc <= 13)      cp_wait<2>();
            else if (kc == 14) cp_wait<1>();
            else               cp_wait<0>();
            __syncthreads();
            const uint32_t* Asl = Ab[kc & 3];
            const uint32_t* Bsl = Bb[kc & 3];
            uint4 af[4], bf[4];
            ldfrag(Asl, Bsl, 0, af, bf);
            if (kc + 3 < 16) stage(kc + 3);     // LSU burst overlaps mma below
            domma(af, bf, c);
            ldfrag(Asl, Bsl, 1, af, bf);
            domma(af, bf, c);
        }
    }
};

// ===========================================================================
// GEMM1/2: chained slotted-A output. 3 CTAs/SM target.
// ===========================================================================
template <int MODE>
__global__ __launch_bounds__(128, 3)
void gemm12_f16(const float* __restrict__ bias)
{
    extern __shared__ uint32_t sm[];
    const int tid  = threadIdx.x;
    const int lane = tid & 31;
    const int wid  = tid >> 5;
    const int tig  = lane & 3;
    const int wm   = wid >> 1;
    const int wn   = wid & 1;
    const int tile = blockIdx.x;
    const int col0 = blockIdx.y * 128;

    const uint32_t* srcA = (MODE == 0 ? g_A1 : g_A2) + (size_t)tile * 16 * BUFU;
    const uint32_t* srcB = (MODE == 0 ? g_WB1 : g_WB2) + (size_t)blockIdx.y * 16 * BUFU;
    uint32_t* dstA = (MODE == 0 ? g_A2 : g_A3) + (size_t)tile * 16 * BUFU;

    float c[4][8][4];
    #pragma unroll
    for (int i = 0; i < 4; i++)
        #pragma unroll
        for (int j = 0; j < 8; j++)
            #pragma unroll
            for (int q = 0; q < 4; q++) c[i][j][q] = 0.f;

    Core core{srcA, srcB,
              {sm, sm + BUFU, sm + 2 * BUFU, sm + 3 * BUFU},
              {sm + 4 * BUFU, sm + 5 * BUFU, sm + 6 * BUFU, sm + 7 * BUFU},
              tid, lane, wm, wn};
    core.run(c);

    #pragma unroll
    for (int mf = 0; mf < 4; mf++) {
        #pragma unroll
        for (int q = 0; q < 4; q++) {
            const int nf0 = 2 * q, nf1 = 2 * q + 1;
            const int K = col0 + wn * 64 + q * 16 + 2 * tig;
            const float b0 = bias[K],     b1 = bias[K + 1];
            const float b8 = bias[K + 8], b9 = bias[K + 9];
            const int kc_o = (col0 >> 5) + wn * 2 + (q >> 1);
            const int slot = (wm * 4 + mf) * 2 + (q & 1);
            uint4 v;
            v.x = pack_h2(lrelu(c[mf][nf0][0] + b0), lrelu(c[mf][nf0][1] + b1));
            v.y = pack_h2(lrelu(c[mf][nf0][2] + b0), lrelu(c[mf][nf0][3] + b1));
            v.z = pack_h2(lrelu(c[mf][nf1][0] + b8), lrelu(c[mf][nf1][1] + b9));
            v.w = pack_h2(lrelu(c[mf][nf1][2] + b8), lrelu(c[mf][nf1][3] + b9));
            *reinterpret_cast<uint4*>(
                &dstA[(size_t)(kc_o * 16 + slot) * SLOTU + lane * 4]) = v;
        }
    }
}

// ===========================================================================
// GEMM3: fused classifier, 3 CTAs/SM target.
// ===========================================================================
__global__ __launch_bounds__(128, 3)
void gemm_head_tc(const float* __restrict__ bc1,
                  const float* __restrict__ Wc2,
                  float* __restrict__ logits)
{
    extern __shared__ uint32_t sm[];
    const int tid  = threadIdx.x;
    const int lane = tid & 31;
    const int wid  = tid >> 5;
    const int g    = lane >> 2;
    const int tig  = lane & 3;
    const int wm   = wid >> 1;
    const int wn   = wid & 1;
    const int tile = blockIdx.x;
    const int hb   = blockIdx.y;
    const int n    = blockIdx.z;
    const int row0 = tile * 128;
    const int h0   = hb * 128;

    const uint32_t* srcA = g_A3 + (size_t)tile * 16 * BUFU;
    const uint32_t* srcB = g_Bh + (size_t)(n * 4 + hb) * 16 * BUFU;

    float c[4][8][4];
    #pragma unroll
    for (int i = 0; i < 4; i++)
        #pragma unroll
        for (int j = 0; j < 8; j++)
            #pragma unroll
            for (int q = 0; q < 4; q++) c[i][j][q] = 0.f;

    Core core{srcA, srcB,
              {sm, sm + BUFU, sm + 2 * BUFU, sm + 3 * BUFU},
              {sm + 4 * BUFU, sm + 5 * BUFU, sm + 6 * BUFU, sm + 7 * BUFU},
              tid, lane, wm, wn};
    core.run(c);

    float p[8];
    #pragma unroll
    for (int i = 0; i < 8; i++) p[i] = 0.f;
    #pragma unroll
    for (int nf = 0; nf < 8; nf++) {
        int h = h0 + wn * 64 + nf * 8 + 2 * tig;
        float b1a = bc1[n * HH + h],     b1b = bc1[n * HH + h + 1];
        float w2a = Wc2[n * HH + h],     w2b = Wc2[n * HH + h + 1];
        #pragma unroll
        for (int mf = 0; mf < 4; mf++) {
            p[2 * mf + 0] += lrelu(c[mf][nf][0] + b1a) * w2a
                           + lrelu(c[mf][nf][1] + b1b) * w2b;
            p[2 * mf + 1] += lrelu(c[mf][nf][2] + b1a) * w2a
                           + lrelu(c[mf][nf][3] + b1b) * w2b;
        }
    }
    #pragma unroll
    for (int i = 0; i < 8; i++) {
        float v = p[i];
        v += __shfl_xor_sync(0xffffffffu, v, 1);
        v += __shfl_xor_sync(0xffffffffu, v, 2);
        if (tig == 0) {
            int mf = i >> 1, half = i & 1;
            int r = row0 + wm * 64 + mf * 16 + g + half * 8;
            int M = (r & 15) * 1024 + (r >> 4);
            atomicAdd(&logits[M * NN + n], v);
        }
    }
}

// full_out += bc2; out[b,n] = sigmoid(diagonal of full_out)
__global__ void finalize_kernel(float* __restrict__ out,
                                const float* __restrict__ bc2)
{
    int idx = blockIdx.x * 256 + threadIdx.x;      // < 262144
    int m = idx >> 4, n = idx & 15;
    float* full = out + MTOT;
    float v = full[idx] + bc2[n];
    full[idx] = v;
    if ((m >> 10) == n) {                           // m = n*1024 + b
        int b = m & 1023;
        out[b * NN + n] = 1.f / (1.f + expf(-v));
    }
}

extern "C" void kernel_launch(void* const* d_in, const int* in_sizes, int n_in,
                              void* d_out, int out_size)
{
    const float* x   = (const float*)d_in[0];
    const float* Ws1 = (const float*)d_in[1];
    const float* bs1 = (const float*)d_in[2];
    const float* Ws2 = (const float*)d_in[3];
    const float* bs2 = (const float*)d_in[4];
    const float* Wc1 = (const float*)d_in[5];
    const float* bc1 = (const float*)d_in[6];
    const float* Wc2 = (const float*)d_in[7];
    const float* bc2 = (const float*)d_in[8];
    float* out = (float*)d_out;

    cudaFuncSetAttribute(gemm12_f16<0>, cudaFuncAttributeMaxDynamicSharedMemorySize, RING_SMEM);
    cudaFuncSetAttribute(gemm12_f16<1>, cudaFuncAttributeMaxDynamicSharedMemorySize, RING_SMEM);
    cudaFuncSetAttribute(gemm_head_tc,  cudaFuncAttributeMaxDynamicSharedMemorySize, RING_SMEM);

    dim3 blk(256);
    prep_all_kernel<<<3200, blk>>>(x, Ws1, Ws2, Wc1, out);
    gemm12_f16<0><<<dim3(128, 4), dim3(128), RING_SMEM>>>(bs1);
    gemm12_f16<1><<<dim3(128, 4), dim3(128), RING_SMEM>>>(bs2);
    gemm_head_tc<<<dim3(128, 4, NN), dim3(128), RING_SMEM>>>(bc1, Wc2, out + MTOT);
    finalize_kernel<<<(MTOT * NN + 255) / 256, blk>>>(out, bc2);
}

// round 16
// speedup vs baseline: 1.7709x; 1.7709x over previous
#include <cuda_runtime.h>
#include <cuda_fp16.h>
#include <math.h>
#include <stdint.h>

// B=1024, D=512, N=16, H=512, M = N*B = 16384
#define DD   512
#define NN   16
#define HH   512
#define MTOT 16384

// Slotted fp16 fragment files (u32 = packed half2).
// A files: [tile(128)][kc(16)][slot(16)][128]; slot = mf*2+ks.
// B files: [blk][kc(16)][slot(16)][128];     slot = n16*2+ks.
__device__ uint32_t g_A1[128 * 16 * 16 * 128];   // x (gathered), GEMM1 A
__device__ uint32_t g_A2[128 * 16 * 16 * 128];   // lrelu(X@Ws1+bs1), GEMM2 A
__device__ uint32_t g_A3[128 * 16 * 16 * 128];   // shared, GEMM3 A (r-ordered)
__device__ uint32_t g_WB1[4  * 16 * 16 * 128];   // Ws1 slotted
__device__ uint32_t g_WB2[4  * 16 * 16 * 128];   // Ws2 slotted
__device__ uint32_t g_Bh [64 * 16 * 16 * 128];   // Wc1 slotted [n*4+hb]

__device__ __forceinline__ float lrelu(float v) { return v >= 0.f ? v : 0.1f * v; }
__device__ __forceinline__ uint32_t pack_h2(float lo, float hi) {
    __half2 h = __floats2half2_rn(lo, hi);
    return *reinterpret_cast<uint32_t*>(&h);
}
__device__ __forceinline__ uint32_t smem_u32(const void* p) {
    uint32_t a;
    asm("{ .reg .u64 t; cvta.to.shared.u64 t, %1; cvt.u32.u64 %0, t; }" : "=r"(a) : "l"(p));
    return a;
}
__device__ __forceinline__ void cpcg16(uint32_t dst, const void* src) {
    asm volatile("cp.async.cg.shared.global [%0], [%1], 16;" :: "r"(dst), "l"(src));
}
__device__ __forceinline__ void cp_commit() {
    asm volatile("cp.async.commit_group;" ::: "memory");
}
template <int N>
__device__ __forceinline__ void cp_wait() {
    asm volatile("cp.async.wait_group %0;" :: "n"(N) : "memory");
}
__device__ __forceinline__ void mma16h(float* c, const uint32_t* a,
                                       uint32_t b0, uint32_t b1) {
    asm volatile(
        "mma.sync.aligned.m16n8k16.row.col.f32.f16.f16.f32 "
        "{%0,%1,%2,%3}, {%4,%5,%6,%7}, {%8,%9}, {%0,%1,%2,%3};"
        : "+f"(c[0]), "+f"(c[1]), "+f"(c[2]), "+f"(c[3])
        : "r"(a[0]), "r"(a[1]), "r"(a[2]), "r"(a[3]), "r"(b0), "r"(b1));
}

#define SLOTU 128
#define BUFU  2048          // u32 per (kc) buffer: 16 slots * 128
#define RING_SMEM 65536     // 4-ring x (A 8KB + B 8KB)

// ===========================================================================
// Fused prep + zero kernel (R15-verbatim — correctness confirmed by rel_err).
// ===========================================================================
__global__ __launch_bounds__(256)
void prep_all_kernel(const float* __restrict__ x,
                     const float* __restrict__ Ws1,
                     const float* __restrict__ Ws2,
                     const float* __restrict__ Wc1,
                     float* __restrict__ out)
{
    __shared__ float sf[16 * 517];      // xA: [n][k], pitch 517
    __shared__ float f2[32 * 130];      // W tiles: [kk][c], pitch 130
    const int blk = blockIdx.x;
    const int tid = threadIdx.x;

    if (blk < 1024) {
        const int b = blk;
        #pragma unroll
        for (int i = 0; i < 32; i++) {
            int e = tid + i * 256;
            int k = e >> 4, n = e & 15;
            sf[n * 517 + k] = x[(size_t)b * 8192 + e];
        }
        __syncthreads();
        const int tile = b >> 3, mf = b & 7;
        #pragma unroll
        for (int i = 0; i < 16; i++) {
            int e2 = tid + i * 256;
            int i128 = e2 & 127, ks = (e2 >> 7) & 1, kc = e2 >> 8;
            int t = i128 >> 2, j = i128 & 3;
            int n = ((j & 1) << 3) + (t >> 2);
            int k = kc * 32 + ks * 16 + (((j >> 1) & 1) << 3) + 2 * (t & 3);
            g_A1[(((size_t)(tile * 16 + kc)) * 16 + (mf * 2 + ks)) * 128 + i128]
                = pack_h2(sf[n * 517 + k], sf[n * 517 + k + 1]);
        }
    } else if (blk < 2048) {
        const int q = blk - 1024;
        const int n = q >> 6, hb = (q >> 4) & 3, kc = q & 15;
        const float* W = Wc1 + (size_t)n * DD * HH;
        #pragma unroll
        for (int i = 0; i < 16; i++) {
            int e = tid + i * 256;
            int kk = e >> 7, c = e & 127;
            f2[kk * 130 + c] = W[(size_t)(kc * 32 + kk) * HH + hb * 128 + c];
        }
        __syncthreads();
        #pragma unroll
        for (int i = 0; i < 8; i++) {
            int e = tid + i * 256;
            int i128 = e & 127, s = e >> 7;
            int n16 = s >> 1, ks = s & 1;
            int t = i128 >> 2, j = i128 & 3;
            int nc = n16 * 16 + (((j >> 1) & 1) << 3) + (t >> 2);
            int kk = ks * 16 + ((j & 1) << 3) + 2 * (t & 3);
            g_Bh[(((size_t)((n * 4 + hb) * 16 + kc)) * 16 + s) * 128 + i128]
                = pack_h2(f2[kk * 130 + nc], f2[(kk + 1) * 130 + nc]);
        }
    } else if (blk < 2176) {
        const int q = blk - 2048;
        const int which = q >> 6, hb = (q >> 4) & 3, kc = q & 15;
        const float* W = which ? Ws2 : Ws1;
        uint32_t* dst  = which ? g_WB2 : g_WB1;
        #pragma unroll
        for (int i = 0; i < 16; i++) {
            int e = tid + i * 256;
            int kk = e >> 7, c = e & 127;
            f2[kk * 130 + c] = W[(size_t)(kc * 32 + kk) * DD + hb * 128 + c];
        }
        __syncthreads();
        #pragma unroll
        for (int i = 0; i < 8; i++) {
            int e = tid + i * 256;
            int i128 = e & 127, s = e >> 7;
            int n16 = s >> 1, ks = s & 1;
            int t = i128 >> 2, j = i128 & 3;
            int nc = n16 * 16 + (((j >> 1) & 1) << 3) + (t >> 2);
            int kk = ks * 16 + ((j & 1) << 3) + 2 * (t & 3);
            dst[(((size_t)(hb * 16 + kc)) * 16 + s) * 128 + i128]
                = pack_h2(f2[kk * 130 + nc], f2[(kk + 1) * 130 + nc]);
        }
    } else {
        int i = (blk - 2176) * 256 + tid;
        (out + MTOT)[i] = 0.f;
    }
}

// ===========================================================================
// Core v3: 256 threads, 8 warps in 2x4 grid (warp tile 64x32).
// Accumulators c[4][4][4] = 64 regs/thread. 4-ring, one sync per kc,
// early stage() issue. Slot layouts unchanged.
// ===========================================================================
struct Core {
    const uint32_t* srcA;
    const uint32_t* srcB;
    uint32_t* Ab[4];
    uint32_t* Bb[4];
    int tid, lane, wm, wn;

    __device__ __forceinline__ void stage(int kc) {
        const int buf = kc & 3;
        const uint32_t* sa = srcA + kc * BUFU;
        const uint32_t* sb = srcB + kc * BUFU;
        uint32_t da = smem_u32(Ab[buf]);
        uint32_t db = smem_u32(Bb[buf]);
        #pragma unroll
        for (int i = 0; i < 2; i++) {
            int ch = tid + i * 256;                 // 512 chunks per buffer
            cpcg16(da + ch * 16, sa + ch * 4);
            cpcg16(db + ch * 16, sb + ch * 4);
        }
        cp_commit();
    }

    __device__ __forceinline__ void ldfrag(const uint32_t* Asl, const uint32_t* Bsl,
                                           int ks, uint4* af, uint4* bf) {
        #pragma unroll
        for (int mfl = 0; mfl < 4; mfl++)
            af[mfl] = *reinterpret_cast<const uint4*>(
                &Asl[((wm * 4 + mfl) * 2 + ks) * SLOTU + lane * 4]);
        #pragma unroll
        for (int np = 0; np < 2; np++)
            bf[np] = *reinterpret_cast<const uint4*>(
                &Bsl[((wn * 2 + np) * 2 + ks) * SLOTU + lane * 4]);
    }

    __device__ __forceinline__ void domma(const uint4* af, const uint4* bf,
                                          float c[4][4][4]) {
        #pragma unroll
        for (int np = 0; np < 2; np++) {
            #pragma unroll
            for (int mfl = 0; mfl < 4; mfl++) {
                const uint32_t* aa = reinterpret_cast<const uint32_t*>(&af[mfl]);
                mma16h(c[mfl][2 * np + 0], aa, bf[np].x, bf[np].y);
                mma16h(c[mfl][2 * np + 1], aa, bf[np].z, bf[np].w);
            }
        }
    }

    __device__ __forceinline__ void run(float c[4][4][4]) {
        stage(0); stage(1); stage(2);
        for (int kc = 0; kc < 16; kc++) {
            if (kc <= 13)      cp_wait<2>();
            else if (kc == 14) cp_wait<1>();
            else               cp_wait<0>();
            __syncthreads();
            const uint32_t* Asl = Ab[kc & 3];
            const uint32_t* Bsl = Bb[kc & 3];
            uint4 af[4], bf[2];
            ldfrag(Asl, Bsl, 0, af, bf);
            if (kc + 3 < 16) stage(kc + 3);     // LSU burst overlaps mma below
            domma(af, bf, c);
            ldfrag(Asl, Bsl, 1, af, bf);
            domma(af, bf, c);
        }
    }
};

// ===========================================================================
// GEMM1/2: chained slotted-A output. 256 threads, 2 CTAs/SM.
// Chaining map (re-derived for 2x4 grid, verified vs R11 both directions):
//   warp covers cols [col0 + wn*32, +32); kc_o = col0/32 + wn;
//   slot = (wm*4+mf)*2 + ksl; intra = lane*4; nf pair (2ksl, 2ksl+1).
// ===========================================================================
template <int MODE>
__global__ __launch_bounds__(256, 2)
void gemm12_f16(const float* __restrict__ bias)
{
    extern __shared__ uint32_t sm[];
    const int tid  = threadIdx.x;
    const int lane = tid & 31;
    const int wid  = tid >> 5;
    const int tig  = lane & 3;
    const int wm   = wid >> 2;             // 0..1
    const int wn   = wid & 3;              // 0..3
    const int tile = blockIdx.x;
    const int col0 = blockIdx.y * 128;

    const uint32_t* srcA = (MODE == 0 ? g_A1 : g_A2) + (size_t)tile * 16 * BUFU;
    const uint32_t* srcB = (MODE == 0 ? g_WB1 : g_WB2) + (size_t)blockIdx.y * 16 * BUFU;
    uint32_t* dstA = (MODE == 0 ? g_A2 : g_A3) + (size_t)tile * 16 * BUFU;

    float c[4][4][4];
    #pragma unroll
    for (int i = 0; i < 4; i++)
        #pragma unroll
        for (int j = 0; j < 4; j++)
            #pragma unroll
            for (int q = 0; q < 4; q++) c[i][j][q] = 0.f;

    Core core{srcA, srcB,
              {sm, sm + BUFU, sm + 2 * BUFU, sm + 3 * BUFU},
              {sm + 4 * BUFU, sm + 5 * BUFU, sm + 6 * BUFU, sm + 7 * BUFU},
              tid, lane, wm, wn};
    core.run(c);

    const int kc_o = (col0 >> 5) + wn;
    #pragma unroll
    for (int mf = 0; mf < 4; mf++) {
        #pragma unroll
        for (int ksl = 0; ksl < 2; ksl++) {
            const int nf0 = 2 * ksl, nf1 = 2 * ksl + 1;
            const int K = col0 + wn * 32 + ksl * 16 + 2 * tig;
            const float b0 = bias[K],     b1 = bias[K + 1];
            const float b8 = bias[K + 8], b9 = bias[K + 9];
            const int slot = (wm * 4 + mf) * 2 + ksl;
            uint4 v;
            v.x = pack_h2(lrelu(c[mf][nf0][0] + b0), lrelu(c[mf][nf0][1] + b1));
            v.y = pack_h2(lrelu(c[mf][nf0][2] + b0), lrelu(c[mf][nf0][3] + b1));
            v.z = pack_h2(lrelu(c[mf][nf1][0] + b8), lrelu(c[mf][nf1][1] + b9));
            v.w = pack_h2(lrelu(c[mf][nf1][2] + b8), lrelu(c[mf][nf1][3] + b9));
            *reinterpret_cast<uint4*>(
                &dstA[(size_t)(kc_o * 16 + slot) * SLOTU + lane * 4]) = v;
        }
    }
}

// ===========================================================================
// GEMM3: fused classifier, 256 threads, 2 CTAs/SM.
// ===========================================================================
__global__ __launch_bounds__(256, 2)
void gemm_head_tc(const float* __restrict__ bc1,
                  const float* __restrict__ Wc2,
                  float* __restrict__ logits)
{
    extern __shared__ uint32_t sm[];
    const int tid  = threadIdx.x;
    const int lane = tid & 31;
    const int wid  = tid >> 5;
    const int g    = lane >> 2;
    const int tig  = lane & 3;
    const int wm   = wid >> 2;             // 0..1
    const int wn   = wid & 3;              // 0..3
    const int tile = blockIdx.x;
    const int hb   = blockIdx.y;
    const int n    = blockIdx.z;
    const int row0 = tile * 128;
    const int h0   = hb * 128;

    const uint32_t* srcA = g_A3 + (size_t)tile * 16 * BUFU;
    const uint32_t* srcB = g_Bh + (size_t)(n * 4 + hb) * 16 * BUFU;

    float c[4][4][4];
    #pragma unroll
    for (int i = 0; i < 4; i++)
        #pragma unroll
        for (int j = 0; j < 4; j++)
            #pragma unroll
            for (int q = 0; q < 4; q++) c[i][j][q] = 0.f;

    Core core{srcA, srcB,
              {sm, sm + BUFU, sm + 2 * BUFU, sm + 3 * BUFU},
              {sm + 4 * BUFU, sm + 5 * BUFU, sm + 6 * BUFU, sm + 7 * BUFU},
              tid, lane, wm, wn};
    core.run(c);

    float p[8];
    #pragma unroll
    for (int i = 0; i < 8; i++) p[i] = 0.f;
    #pragma unroll
    for (int nf = 0; nf < 4; nf++) {
        int h = h0 + wn * 32 + nf * 8 + 2 * tig;
        float b1a = bc1[n * HH + h],     b1b = bc1[n * HH + h + 1];
        float w2a = Wc2[n * HH + h],     w2b = Wc2[n * HH + h + 1];
        #pragma unroll
        for (int mf = 0; mf < 4; mf++) {
            p[2 * mf + 0] += lrelu(c[mf][nf][0] + b1a) * w2a
                           + lrelu(c[mf][nf][1] + b1b) * w2b;
            p[2 * mf + 1] += lrelu(c[mf][nf][2] + b1a) * w2a
                           + lrelu(c[mf][nf][3] + b1b) * w2b;
        }
    }
    #pragma unroll
    for (int i = 0; i < 8; i++) {
        float v = p[i];
        v += __shfl_xor_sync(0xffffffffu, v, 1);
        v += __shfl_xor_sync(0xffffffffu, v, 2);
        if (tig == 0) {
            int mf = i >> 1, half = i & 1;
            int r = row0 + wm * 64 + mf * 16 + g + half * 8;
            int M = (r & 15) * 1024 + (r >> 4);
            atomicAdd(&logits[M * NN + n], v);
        }
    }
}

// full_out += bc2; out[b,n] = sigmoid(diagonal of full_out)
__global__ void finalize_kernel(float* __restrict__ out,
                                const float* __restrict__ bc2)
{
    int idx = blockIdx.x * 256 + threadIdx.x;      // < 262144
    int m = idx >> 4, n = idx & 15;
    float* full = out + MTOT;
    float v = full[idx] + bc2[n];
    full[idx] = v;
    if ((m >> 10) == n) {                           // m = n*1024 + b
        int b = m & 1023;
        out[b * NN + n] = 1.f / (1.f + expf(-v));
    }
}

extern "C" void kernel_launch(void* const* d_in, const int* in_sizes, int n_in,
                              void* d_out, int out_size)
{
    const float* x   = (const float*)d_in[0];
    const float* Ws1 = (const float*)d_in[1];
    const float* bs1 = (const float*)d_in[2];
    const float* Ws2 = (const float*)d_in[3];
    const float* bs2 = (const float*)d_in[4];
    const float* Wc1 = (const float*)d_in[5];
    const float* bc1 = (const float*)d_in[6];
    const float* Wc2 = (const float*)d_in[7];
    const float* bc2 = (const float*)d_in[8];
    float* out = (float*)d_out;

    cudaFuncSetAttribute(gemm12_f16<0>, cudaFuncAttributeMaxDynamicSharedMemorySize, RING_SMEM);
    cudaFuncSetAttribute(gemm12_f16<1>, cudaFuncAttributeMaxDynamicSharedMemorySize, RING_SMEM);
    cudaFuncSetAttribute(gemm_head_tc,  cudaFuncAttributeMaxDynamicSharedMemorySize, RING_SMEM);

    dim3 blk(256);
    prep_all_kernel<<<3200, blk>>>(x, Ws1, Ws2, Wc1, out);
    gemm12_f16<0><<<dim3(128, 4), dim3(256), RING_SMEM>>>(bs1);
    gemm12_f16<1><<<dim3(128, 4), dim3(256), RING_SMEM>>>(bs2);
    gemm_head_tc<<<dim3(128, 4, NN), dim3(256), RING_SMEM>>>(bc1, Wc2, out + MTOT);
    finalize_kernel<<<(MTOT * NN + 255) / 256, blk>>>(out, bc2);
}